// round 9
// baseline (speedup 1.0000x reference)
#include <cuda_runtime.h>
#include <cstdint>

#define NUM_SRC 16384
#define NUM_DST 8192
#define N_NBR 50
#define D_FEAT 64
#define K_SEL 10
#define SPITCH 51
#define TOTAL_IDX (NUM_DST * N_NBR)
#define PIPE_GRID 152
#define ROW_BYTES (NUM_SRC * 4)   // 64 KB
#define NSTAGE 3
#define USE_CAP 96                // >= max row degree (Poisson(25), ~14 sigma margin)

__device__ int   g_deg[NUM_SRC];
__device__ int   g_idx[TOTAL_IDX];
__device__ int   g_uses[NUM_SRC * USE_CAP];
__device__ float g_tile[(size_t)NUM_DST * N_NBR * N_NBR];   // 82 MB scratch
__device__ int   g_is64;

__device__ __forceinline__ uint32_t smem_u32(const void* p) {
    uint32_t a;
    asm("{ .reg .u64 t; cvta.to.shared.u64 t, %1; cvt.u32.u64 %0, t; }" : "=r"(a) : "l"(p));
    return a;
}
__device__ __forceinline__ void mbar_init(uint32_t mbar, uint32_t cnt) {
    asm volatile("mbarrier.init.shared.b64 [%0], %1;" :: "r"(mbar), "r"(cnt) : "memory");
}
__device__ __forceinline__ void mbar_expect_tx(uint32_t mbar, uint32_t bytes) {
    asm volatile("mbarrier.arrive.expect_tx.shared.b64 _, [%0], %1;" :: "r"(mbar), "r"(bytes) : "memory");
}
__device__ __forceinline__ void mbar_wait(uint32_t mbar, uint32_t parity) {
    uint32_t done;
    asm volatile(
        "{ .reg .pred p;\n"
        "mbarrier.try_wait.parity.acquire.cta.shared::cta.b64 p, [%1], %2;\n"
        "selp.b32 %0, 1, 0, p; }"
        : "=r"(done) : "r"(mbar), "r"(parity) : "memory");
    if (!done) {
        asm volatile(
            "{ .reg .pred P1;\n"
            "W%=:\n"
            "mbarrier.try_wait.parity.acquire.cta.shared::cta.b64 P1, [%0], %1, 0x989680;\n"
            "@P1 bra.uni D%=;\n"
            "bra.uni W%=;\n"
            "D%=: }"
            :: "r"(mbar), "r"(parity) : "memory");
    }
}
__device__ __forceinline__ void bulk_g2s(uint32_t dst, const void* src, uint32_t bytes, uint32_t mbar) {
    asm volatile(
        "cp.async.bulk.shared::cluster.global.mbarrier::complete_tx::bytes [%0], [%1], %2, [%3];"
        :: "r"(dst), "l"(src), "r"(bytes), "r"(mbar) : "memory");
}

// K1: zero degree array + int64/int32 detection
__global__ void prep_zero_detect(const int* __restrict__ raw) {
    int i = blockIdx.x * blockDim.x + threadIdx.x;
    if (i < NUM_SRC) g_deg[i] = 0;
    if (blockIdx.x == 0 && threadIdx.x < 32) {
        int bad = 0;
        #pragma unroll
        for (int u = 0; u < 16; u++)
            bad |= (raw[2 * (threadIdx.x * 16 + u) + 1] != 0);
        unsigned m = __ballot_sync(0xffffffffu, bad);
        if (threadIdx.x == 0) g_is64 = (m == 0u);
    }
}

// K2: normalize indices + degree histogram + direct use-list fill
__global__ void prep_convert_hist_fill(const void* __restrict__ raw) {
    int t = blockIdx.x * blockDim.x + threadIdx.x;
    if (t < TOTAL_IDX) {
        int v;
        if (g_is64) v = (int)((const long long*)raw)[t];
        else        v = ((const int*)raw)[t];
        g_idx[t] = v;
        int pos = atomicAdd(&g_deg[v], 1);
        if (pos < USE_CAP) g_uses[v * USE_CAP + pos] = t;
    }
}

// K3: persistent triple-buffered TMA row streamer, 32 consumer warps,
//     use-lists prefetched to smem (unchanged from R8 — at its streaming floor)
__global__ __launch_bounds__(1024) void row_gather_pipe(const float* __restrict__ table) {
    extern __shared__ __align__(1024) unsigned char smem_raw[];
    const uint32_t base = smem_u32(smem_raw);
    int*  s_uses = (int*)(smem_raw + 64);           // 2 * USE_CAP ints
    int*  s_n    = (int*)(smem_raw + 64 + 2 * USE_CAP * 4);
    uint32_t mbar[NSTAGE], bufadr[NSTAGE];
    float* bufs[NSTAGE];
    #pragma unroll
    for (int s = 0; s < NSTAGE; s++) {
        mbar[s]   = base + 8 * s;
        bufadr[s] = base + 1024 + s * ROW_BYTES;
        bufs[s]   = (float*)(smem_raw + 1024 + s * ROW_BYTES);
    }

    const int tid  = threadIdx.x;
    const int wid  = tid >> 5;
    const int lane = tid & 31;

    if (tid == 0) {
        #pragma unroll
        for (int s = 0; s < NSTAGE; s++) mbar_init(mbar[s], 1);
    }
    __syncthreads();

    if (tid == 0) {
        #pragma unroll
        for (int p = 0; p < 2; p++) {
            int r = blockIdx.x + p * PIPE_GRID;
            if (r < NUM_SRC) {
                mbar_expect_tx(mbar[p], ROW_BYTES);
                #pragma unroll
                for (int c = 0; c < 4; c++)
                    bulk_g2s(bufadr[p] + c * (ROW_BYTES / 4),
                             (const char*)(table + (size_t)r * NUM_SRC) + c * (ROW_BYTES / 4),
                             ROW_BYTES / 4, mbar[p]);
            }
        }
    }
    if (wid == 0) {
        int r = blockIdx.x;
        int d = g_deg[r]; if (d > USE_CAP) d = USE_CAP;
        if (lane == 0) s_n[0] = d;
        for (int u = lane; u < d; u += 32) s_uses[u] = g_uses[r * USE_CAP + u];
    }
    __syncthreads();

    int ph[NSTAGE] = {0, 0, 0};
    int i = 0;
    for (int row = blockIdx.x; row < NUM_SRC; row += PIPE_GRID, i++) {
        const int st   = i % NSTAGE;
        const int slot = i & 1;

        int nxt2 = row + 2 * PIPE_GRID;
        if (nxt2 < NUM_SRC && tid == 0) {
            int ns = (i + 2) % NSTAGE;
            mbar_expect_tx(mbar[ns], ROW_BYTES);
            #pragma unroll
            for (int c = 0; c < 4; c++)
                bulk_g2s(bufadr[ns] + c * (ROW_BYTES / 4),
                         (const char*)(table + (size_t)nxt2 * NUM_SRC) + c * (ROW_BYTES / 4),
                         ROW_BYTES / 4, mbar[ns]);
        }

        if (wid == 31) {
            int r = row + PIPE_GRID;
            int d = 0;
            if (r < NUM_SRC) { d = g_deg[r]; if (d > USE_CAP) d = USE_CAP; }
            if (lane == 0) s_n[slot ^ 1] = d;
            for (int u = lane; u < d; u += 32)
                s_uses[(slot ^ 1) * USE_CAP + u] = g_uses[r * USE_CAP + u];
        }

        mbar_wait(mbar[st], ph[st]);
        ph[st] ^= 1;
        const float* srow = bufs[st];

        const int n = s_n[slot];
        for (int u = wid; u < n; u += 32) {
            int t   = s_uses[slot * USE_CAP + u];   // t = b*50 + i
            int bse = t - (t % N_NBR);              // b*50
            float* out = &g_tile[(size_t)t * N_NBR];
            if (lane < N_NBR) {
                out[lane] = srow[g_idx[bse + lane]];
                int j = lane + 32;
                if (j < N_NBR) out[j] = srow[g_idx[bse + j]];
            }
        }
        __syncthreads();
    }
}

// K4: greedy max-coverage, register-resident rows, 2-warp parallel gains.
__global__ __launch_bounds__(128) void dgrec_greedy_kernel(
    const float* __restrict__ h_src,
    float* __restrict__ out)
{
    __shared__ float s[N_NBR * SPITCH];
    __shared__ float cache[N_NBR];
    __shared__ float wg[2];
    __shared__ int   wi[2];
    __shared__ int   sels[K_SEL];
    __shared__ int   sidx[K_SEL];
    __shared__ float nrmk[K_SEL];

    const int b   = blockIdx.x;
    const int tid = threadIdx.x;

    // float4 coalesced tile load (b*2500*4 bytes is 16B-aligned), re-pitch to 51
    const float4* tsrc4 = (const float4*)(g_tile + (size_t)b * N_NBR * N_NBR);
    for (int q = tid; q < (N_NBR * N_NBR) / 4; q += 128) {
        float4 v = tsrc4[q];
        int t = q * 4;
        int i0 = t / N_NBR;         s[i0 * SPITCH + (t - i0 * N_NBR)] = v.x;
        int i1 = (t + 1) / N_NBR;   s[i1 * SPITCH + (t + 1 - i1 * N_NBR)] = v.y;
        int i2 = (t + 2) / N_NBR;   s[i2 * SPITCH + (t + 2 - i2 * N_NBR)] = v.z;
        int i3 = (t + 3) / N_NBR;   s[i3 * SPITCH + (t + 3 - i3 * N_NBR)] = v.w;
    }
    if (tid < N_NBR) cache[tid] = 0.0f;
    __syncthreads();

    // thread tid (<50) owns row tid in registers
    float r[N_NBR];
    if (tid < N_NBR) {
        #pragma unroll
        for (int j = 0; j < N_NBR; j++) r[j] = s[tid * SPITCH + j];
    }

    for (int k = 0; k < K_SEL; k++) {
        float g = -1.0f;
        if (tid < N_NBR) {
            g = 0.0f;
            // single ascending chain: bit-identical to validated arithmetic
            #pragma unroll
            for (int j = 0; j < N_NBR; j++)
                g += fmaxf(r[j] - cache[j], 0.0f);
        }
        if (tid < 64) {
            int idx = tid;
            #pragma unroll
            for (int o = 16; o > 0; o >>= 1) {
                float og = __shfl_down_sync(0xffffffffu, g, o);
                int   oi = __shfl_down_sync(0xffffffffu, idx, o);
                if (og > g || (og == g && oi < idx)) { g = og; idx = oi; }
            }
            if ((tid & 31) == 0) { wg[tid >> 5] = g; wi[tid >> 5] = idx; }
        }
        __syncthreads();
        // cross-warp combine: strict > so tie goes to warp0 (smaller indices) —
        // preserves jnp.argmax first-occurrence semantics
        int sel = (wg[1] > wg[0]) ? wi[1] : wi[0];
        if (tid == 0) sels[k] = sel;
        if (tid < N_NBR)
            cache[tid] = fmaxf(cache[tid], s[sel * SPITCH + tid]);
        __syncthreads();
    }

    if (tid < K_SEL) {
        int idx2 = g_idx[b * N_NBR + sels[tid]];
        sidx[tid] = idx2;
        int d = g_deg[idx2];
        if (d < 1) d = 1;
        nrmk[tid] = rsqrtf((float)d);
    }
    __syncthreads();

    if (tid < D_FEAT) {
        float acc = 0.0f;
        #pragma unroll
        for (int k = 0; k < K_SEL; k++)
            acc += h_src[(size_t)sidx[k] * D_FEAT + tid] * nrmk[k];
        out[(size_t)b * D_FEAT + tid] = acc * 0.1414213562373095f; // 50^-0.5
    }
}

extern "C" void kernel_launch(void* const* d_in, const int* in_sizes, int n_in,
                              void* d_out, int out_size) {
    const float* h_src = nullptr;
    const float* table = nullptr;
    const void*  nbrs  = nullptr;
    for (int i = 0; i < n_in; i++) {
        long long sz = in_sizes[i];
        if (sz == (long long)NUM_SRC * NUM_SRC)      table = (const float*)d_in[i];
        else if (sz == (long long)NUM_SRC * D_FEAT)  h_src = (const float*)d_in[i];
        else if (sz == (long long)TOTAL_IDX)         nbrs  = d_in[i];
    }
    float* out = (float*)d_out;

    const int smem_bytes = 1024 + NSTAGE * ROW_BYTES;
    cudaFuncSetAttribute(row_gather_pipe, cudaFuncAttributeMaxDynamicSharedMemorySize,
                         smem_bytes);

    prep_zero_detect<<<(NUM_SRC + 255) / 256, 256>>>((const int*)nbrs);
    prep_convert_hist_fill<<<(TOTAL_IDX + 255) / 256, 256>>>(nbrs);
    row_gather_pipe<<<PIPE_GRID, 1024, smem_bytes>>>(table);
    dgrec_greedy_kernel<<<NUM_DST, 128>>>(h_src, out);
}

// round 10
// speedup vs baseline: 1.0350x; 1.0350x over previous
#include <cuda_runtime.h>
#include <cstdint>

#define NUM_SRC 16384
#define NUM_DST 8192
#define N_NBR 50
#define D_FEAT 64
#define K_SEL 10
#define TOTAL_IDX (NUM_DST * N_NBR)
#define PIPE_GRID 152
#define ROW_BYTES (NUM_SRC * 4)   // 64 KB
#define NSTAGE 3
#define USE_CAP 96

// per-warp greedy smem layout (floats): tile 50*52=2600 | cache 56 | sels 10 | sidx 10 | nrmk 10 | pad
#define WPITCH 52
#define W_TILE 2600
#define W_CACHE (W_TILE)            // +56
#define W_SELS  (W_TILE + 56)       // +10 (as int)
#define W_SIDX  (W_TILE + 66)       // +10 (as int)
#define W_NRMK  (W_TILE + 76)       // +10
#define W_STRIDE 2688               // floats, 10752 B (16B aligned)

__device__ int   g_deg[NUM_SRC];
__device__ int   g_idx[TOTAL_IDX];
__device__ int   g_uses[NUM_SRC * USE_CAP];
__device__ float g_tile[(size_t)NUM_DST * N_NBR * N_NBR];   // 82 MB scratch
__device__ int   g_is64;

__device__ __forceinline__ uint32_t smem_u32(const void* p) {
    uint32_t a;
    asm("{ .reg .u64 t; cvta.to.shared.u64 t, %1; cvt.u32.u64 %0, t; }" : "=r"(a) : "l"(p));
    return a;
}
__device__ __forceinline__ void mbar_init(uint32_t mbar, uint32_t cnt) {
    asm volatile("mbarrier.init.shared.b64 [%0], %1;" :: "r"(mbar), "r"(cnt) : "memory");
}
__device__ __forceinline__ void mbar_expect_tx(uint32_t mbar, uint32_t bytes) {
    asm volatile("mbarrier.arrive.expect_tx.shared.b64 _, [%0], %1;" :: "r"(mbar), "r"(bytes) : "memory");
}
__device__ __forceinline__ void mbar_wait(uint32_t mbar, uint32_t parity) {
    uint32_t done;
    asm volatile(
        "{ .reg .pred p;\n"
        "mbarrier.try_wait.parity.acquire.cta.shared::cta.b64 p, [%1], %2;\n"
        "selp.b32 %0, 1, 0, p; }"
        : "=r"(done) : "r"(mbar), "r"(parity) : "memory");
    if (!done) {
        asm volatile(
            "{ .reg .pred P1;\n"
            "W%=:\n"
            "mbarrier.try_wait.parity.acquire.cta.shared::cta.b64 P1, [%0], %1, 0x989680;\n"
            "@P1 bra.uni D%=;\n"
            "bra.uni W%=;\n"
            "D%=: }"
            :: "r"(mbar), "r"(parity) : "memory");
    }
}
__device__ __forceinline__ void bulk_g2s(uint32_t dst, const void* src, uint32_t bytes, uint32_t mbar) {
    asm volatile(
        "cp.async.bulk.shared::cluster.global.mbarrier::complete_tx::bytes [%0], [%1], %2, [%3];"
        :: "r"(dst), "l"(src), "r"(bytes), "r"(mbar) : "memory");
}

// K1: zero degree array + int64/int32 detection
__global__ void prep_zero_detect(const int* __restrict__ raw) {
    int i = blockIdx.x * blockDim.x + threadIdx.x;
    if (i < NUM_SRC) g_deg[i] = 0;
    if (blockIdx.x == 0 && threadIdx.x < 32) {
        int bad = 0;
        #pragma unroll
        for (int u = 0; u < 16; u++)
            bad |= (raw[2 * (threadIdx.x * 16 + u) + 1] != 0);
        unsigned m = __ballot_sync(0xffffffffu, bad);
        if (threadIdx.x == 0) g_is64 = (m == 0u);
    }
}

// K2: normalize indices + degree histogram + direct use-list fill
__global__ void prep_convert_hist_fill(const void* __restrict__ raw) {
    int t = blockIdx.x * blockDim.x + threadIdx.x;
    if (t < TOTAL_IDX) {
        int v;
        if (g_is64) v = (int)((const long long*)raw)[t];
        else        v = ((const int*)raw)[t];
        g_idx[t] = v;
        int pos = atomicAdd(&g_deg[v], 1);
        if (pos < USE_CAP) g_uses[v * USE_CAP + pos] = t;
    }
}

// K3: persistent triple-buffered TMA row streamer (unchanged — at streaming floor)
__global__ __launch_bounds__(1024) void row_gather_pipe(const float* __restrict__ table) {
    extern __shared__ __align__(1024) unsigned char smem_raw[];
    const uint32_t base = smem_u32(smem_raw);
    int*  s_uses = (int*)(smem_raw + 64);
    int*  s_n    = (int*)(smem_raw + 64 + 2 * USE_CAP * 4);
    uint32_t mbar[NSTAGE], bufadr[NSTAGE];
    float* bufs[NSTAGE];
    #pragma unroll
    for (int s = 0; s < NSTAGE; s++) {
        mbar[s]   = base + 8 * s;
        bufadr[s] = base + 1024 + s * ROW_BYTES;
        bufs[s]   = (float*)(smem_raw + 1024 + s * ROW_BYTES);
    }

    const int tid  = threadIdx.x;
    const int wid  = tid >> 5;
    const int lane = tid & 31;

    if (tid == 0) {
        #pragma unroll
        for (int s = 0; s < NSTAGE; s++) mbar_init(mbar[s], 1);
    }
    __syncthreads();

    if (tid == 0) {
        #pragma unroll
        for (int p = 0; p < 2; p++) {
            int r = blockIdx.x + p * PIPE_GRID;
            if (r < NUM_SRC) {
                mbar_expect_tx(mbar[p], ROW_BYTES);
                #pragma unroll
                for (int c = 0; c < 4; c++)
                    bulk_g2s(bufadr[p] + c * (ROW_BYTES / 4),
                             (const char*)(table + (size_t)r * NUM_SRC) + c * (ROW_BYTES / 4),
                             ROW_BYTES / 4, mbar[p]);
            }
        }
    }
    if (wid == 0) {
        int r = blockIdx.x;
        int d = g_deg[r]; if (d > USE_CAP) d = USE_CAP;
        if (lane == 0) s_n[0] = d;
        for (int u = lane; u < d; u += 32) s_uses[u] = g_uses[r * USE_CAP + u];
    }
    __syncthreads();

    int ph[NSTAGE] = {0, 0, 0};
    int i = 0;
    for (int row = blockIdx.x; row < NUM_SRC; row += PIPE_GRID, i++) {
        const int st   = i % NSTAGE;
        const int slot = i & 1;

        int nxt2 = row + 2 * PIPE_GRID;
        if (nxt2 < NUM_SRC && tid == 0) {
            int ns = (i + 2) % NSTAGE;
            mbar_expect_tx(mbar[ns], ROW_BYTES);
            #pragma unroll
            for (int c = 0; c < 4; c++)
                bulk_g2s(bufadr[ns] + c * (ROW_BYTES / 4),
                         (const char*)(table + (size_t)nxt2 * NUM_SRC) + c * (ROW_BYTES / 4),
                         ROW_BYTES / 4, mbar[ns]);
        }

        if (wid == 31) {
            int r = row + PIPE_GRID;
            int d = 0;
            if (r < NUM_SRC) { d = g_deg[r]; if (d > USE_CAP) d = USE_CAP; }
            if (lane == 0) s_n[slot ^ 1] = d;
            for (int u = lane; u < d; u += 32)
                s_uses[(slot ^ 1) * USE_CAP + u] = g_uses[r * USE_CAP + u];
        }

        mbar_wait(mbar[st], ph[st]);
        ph[st] ^= 1;
        const float* srow = bufs[st];

        const int n = s_n[slot];
        for (int u = wid; u < n; u += 32) {
            int t   = s_uses[slot * USE_CAP + u];
            int bse = t - (t % N_NBR);
            float* out = &g_tile[(size_t)t * N_NBR];
            if (lane < N_NBR) {
                out[lane] = srow[g_idx[bse + lane]];
                int j = lane + 32;
                if (j < N_NBR) out[j] = srow[g_idx[bse + j]];
            }
        }
        __syncthreads();
    }
}

// K4: greedy — one warp per dst tile, 4 independent warps per CTA, no block barriers.
__global__ __launch_bounds__(128) void dgrec_greedy_kernel(
    const float* __restrict__ h_src,
    float* __restrict__ out)
{
    __shared__ __align__(16) float sm[4 * W_STRIDE];   // 43008 B

    const int w    = threadIdx.x >> 5;
    const int lane = threadIdx.x & 31;
    const int b    = blockIdx.x * 4 + w;

    float* s     = &sm[w * W_STRIDE];          // tile, pitch 52, rows 16B-aligned
    float* cache = &sm[w * W_STRIDE + W_CACHE];
    int*   sels  = (int*)&sm[w * W_STRIDE + W_SELS];
    int*   sidx  = (int*)&sm[w * W_STRIDE + W_SIDX];
    float* nrmk  = &sm[w * W_STRIDE + W_NRMK];

    // Warp-coalesced tile load: 625 float4, scatter to pitch-52 layout
    {
        const float4* tsrc4 = (const float4*)(g_tile + (size_t)b * N_NBR * N_NBR);
        for (int q = lane; q < (N_NBR * N_NBR) / 4; q += 32) {
            float4 v = tsrc4[q];
            int t = q * 4;
            int i0 = t / N_NBR;         s[i0 * WPITCH + (t     - i0 * N_NBR)] = v.x;
            int i1 = (t + 1) / N_NBR;   s[i1 * WPITCH + (t + 1 - i1 * N_NBR)] = v.y;
            int i2 = (t + 2) / N_NBR;   s[i2 * WPITCH + (t + 2 - i2 * N_NBR)] = v.z;
            int i3 = (t + 3) / N_NBR;   s[i3 * WPITCH + (t + 3 - i3 * N_NBR)] = v.w;
        }
        // zero cache (52 floats incl. float4-read padding)
        cache[lane] = 0.0f;
        if (lane < 20) cache[lane + 32] = 0.0f;
    }
    __syncwarp();

    const int row0   = lane;
    const int row1   = lane + 32;
    const bool has1  = (row1 < N_NBR);
    const float4* s0 = (const float4*)&s[row0 * WPITCH];
    const float4* s1 = (const float4*)&s[(has1 ? row1 : row0) * WPITCH];
    const float4* c4 = (const float4*)cache;

    for (int k = 0; k < K_SEL; k++) {
        // gains: ascending j, single accumulation chain per row (bit-identical order)
        float g0 = 0.0f, g1 = 0.0f;
        #pragma unroll
        for (int q = 0; q < 12; q++) {          // j = 0..47
            float4 c = c4[q];
            float4 a = s0[q];
            float4 d = s1[q];
            g0 += fmaxf(a.x - c.x, 0.0f);  g1 += fmaxf(d.x - c.x, 0.0f);
            g0 += fmaxf(a.y - c.y, 0.0f);  g1 += fmaxf(d.y - c.y, 0.0f);
            g0 += fmaxf(a.z - c.z, 0.0f);  g1 += fmaxf(d.z - c.z, 0.0f);
            g0 += fmaxf(a.w - c.w, 0.0f);  g1 += fmaxf(d.w - c.w, 0.0f);
        }
        #pragma unroll
        for (int j = 48; j < N_NBR; j++) {      // tail
            float c = cache[j];
            g0 += fmaxf(s[row0 * WPITCH + j] - c, 0.0f);
            g1 += fmaxf(s[(has1 ? row1 : row0) * WPITCH + j] - c, 0.0f);
        }

        // local pair: tie -> row0 (first occurrence)
        float g; int idx;
        if (has1 && g1 > g0) { g = g1; idx = row1; }
        else                 { g = g0; idx = row0; }
        // warp argmax, tie -> smaller index
        #pragma unroll
        for (int o = 16; o > 0; o >>= 1) {
            float og = __shfl_down_sync(0xffffffffu, g, o);
            int   oi = __shfl_down_sync(0xffffffffu, idx, o);
            if (og > g || (og == g && oi < idx)) { g = og; idx = oi; }
        }
        int sel = __shfl_sync(0xffffffffu, idx, 0);
        if (lane == 0) sels[k] = sel;

        // cache = max(cache, s[sel])
        const float* srw = &s[sel * WPITCH];
        cache[lane] = fmaxf(cache[lane], srw[lane]);
        if (has1) cache[row1] = fmaxf(cache[row1], srw[row1]);
        __syncwarp();
    }

    if (lane < K_SEL) {
        int idx2 = g_idx[b * N_NBR + sels[lane]];
        sidx[lane] = idx2;
        int d = g_deg[idx2];
        if (d < 1) d = 1;
        nrmk[lane] = rsqrtf((float)d);
    }
    __syncwarp();

    // output: lane handles features lane and lane+32 (coalesced 128B stores)
    float acc0 = 0.0f, acc1 = 0.0f;
    #pragma unroll
    for (int k = 0; k < K_SEL; k++) {
        const float* hr = &h_src[(size_t)sidx[k] * D_FEAT];
        float nk = nrmk[k];
        acc0 += hr[lane]      * nk;
        acc1 += hr[lane + 32] * nk;
    }
    out[(size_t)b * D_FEAT + lane]      = acc0 * 0.1414213562373095f;
    out[(size_t)b * D_FEAT + lane + 32] = acc1 * 0.1414213562373095f;
}

extern "C" void kernel_launch(void* const* d_in, const int* in_sizes, int n_in,
                              void* d_out, int out_size) {
    const float* h_src = nullptr;
    const float* table = nullptr;
    const void*  nbrs  = nullptr;
    for (int i = 0; i < n_in; i++) {
        long long sz = in_sizes[i];
        if (sz == (long long)NUM_SRC * NUM_SRC)      table = (const float*)d_in[i];
        else if (sz == (long long)NUM_SRC * D_FEAT)  h_src = (const float*)d_in[i];
        else if (sz == (long long)TOTAL_IDX)         nbrs  = d_in[i];
    }
    float* out = (float*)d_out;

    const int smem_bytes = 1024 + NSTAGE * ROW_BYTES;
    cudaFuncSetAttribute(row_gather_pipe, cudaFuncAttributeMaxDynamicSharedMemorySize,
                         smem_bytes);

    prep_zero_detect<<<(NUM_SRC + 255) / 256, 256>>>((const int*)nbrs);
    prep_convert_hist_fill<<<(TOTAL_IDX + 255) / 256, 256>>>(nbrs);
    row_gather_pipe<<<PIPE_GRID, 1024, smem_bytes>>>(table);
    dgrec_greedy_kernel<<<NUM_DST / 4, 128>>>(h_src, out);
}

// round 11
// speedup vs baseline: 1.0760x; 1.0397x over previous
#include <cuda_runtime.h>
#include <cstdint>

#define NUM_SRC 16384
#define NUM_DST 8192
#define N_NBR 50
#define D_FEAT 64
#define K_SEL 10
#define TOTAL_IDX (NUM_DST * N_NBR)
#define PIPE_GRID 152
#define ROW_BYTES (NUM_SRC * 4)   // 64 KB
#define NSTAGE 3
#define USE_CAP 96

// per-warp greedy smem layout (floats): tile 50*52=2600 | cache 56 | sels 10 | sidx 10 | nrmk 10 | pad
#define WPITCH 52
#define W_TILE 2600
#define W_CACHE (W_TILE)
#define W_SELS  (W_TILE + 56)
#define W_SIDX  (W_TILE + 66)
#define W_NRMK  (W_TILE + 76)
#define W_STRIDE 2688               // floats, 10752 B

__device__ int   g_deg[NUM_SRC];
__device__ int   g_idx[TOTAL_IDX];
__device__ int   g_uses[NUM_SRC * USE_CAP];
__device__ float g_tile[(size_t)NUM_DST * N_NBR * N_NBR];   // 82 MB scratch
__device__ int   g_is64;

__device__ __forceinline__ uint32_t smem_u32(const void* p) {
    uint32_t a;
    asm("{ .reg .u64 t; cvta.to.shared.u64 t, %1; cvt.u32.u64 %0, t; }" : "=r"(a) : "l"(p));
    return a;
}
__device__ __forceinline__ void mbar_init(uint32_t mbar, uint32_t cnt) {
    asm volatile("mbarrier.init.shared.b64 [%0], %1;" :: "r"(mbar), "r"(cnt) : "memory");
}
__device__ __forceinline__ void mbar_expect_tx(uint32_t mbar, uint32_t bytes) {
    asm volatile("mbarrier.arrive.expect_tx.shared.b64 _, [%0], %1;" :: "r"(mbar), "r"(bytes) : "memory");
}
__device__ __forceinline__ void mbar_wait(uint32_t mbar, uint32_t parity) {
    uint32_t done;
    asm volatile(
        "{ .reg .pred p;\n"
        "mbarrier.try_wait.parity.acquire.cta.shared::cta.b64 p, [%1], %2;\n"
        "selp.b32 %0, 1, 0, p; }"
        : "=r"(done) : "r"(mbar), "r"(parity) : "memory");
    if (!done) {
        asm volatile(
            "{ .reg .pred P1;\n"
            "W%=:\n"
            "mbarrier.try_wait.parity.acquire.cta.shared::cta.b64 P1, [%0], %1, 0x989680;\n"
            "@P1 bra.uni D%=;\n"
            "bra.uni W%=;\n"
            "D%=: }"
            :: "r"(mbar), "r"(parity) : "memory");
    }
}
__device__ __forceinline__ void bulk_g2s(uint32_t dst, const void* src, uint32_t bytes, uint32_t mbar) {
    asm volatile(
        "cp.async.bulk.shared::cluster.global.mbarrier::complete_tx::bytes [%0], [%1], %2, [%3];"
        :: "r"(dst), "l"(src), "r"(bytes), "r"(mbar) : "memory");
}

// K1: zero degree array + int64/int32 detection
__global__ void prep_zero_detect(const int* __restrict__ raw) {
    int i = blockIdx.x * blockDim.x + threadIdx.x;
    if (i < NUM_SRC) g_deg[i] = 0;
    if (blockIdx.x == 0 && threadIdx.x < 32) {
        int bad = 0;
        #pragma unroll
        for (int u = 0; u < 16; u++)
            bad |= (raw[2 * (threadIdx.x * 16 + u) + 1] != 0);
        unsigned m = __ballot_sync(0xffffffffu, bad);
        if (threadIdx.x == 0) g_is64 = (m == 0u);
    }
}

// K2: normalize indices + degree histogram + direct use-list fill
__global__ void prep_convert_hist_fill(const void* __restrict__ raw) {
    int t = blockIdx.x * blockDim.x + threadIdx.x;
    if (t < TOTAL_IDX) {
        int v;
        if (g_is64) v = (int)((const long long*)raw)[t];
        else        v = ((const int*)raw)[t];
        g_idx[t] = v;
        int pos = atomicAdd(&g_deg[v], 1);
        if (pos < USE_CAP) g_uses[v * USE_CAP + pos] = t;
    }
}

// K3: persistent triple-buffered TMA row streamer (unchanged)
__global__ __launch_bounds__(1024) void row_gather_pipe(const float* __restrict__ table) {
    extern __shared__ __align__(1024) unsigned char smem_raw[];
    const uint32_t base = smem_u32(smem_raw);
    int*  s_uses = (int*)(smem_raw + 64);
    int*  s_n    = (int*)(smem_raw + 64 + 2 * USE_CAP * 4);
    uint32_t mbar[NSTAGE], bufadr[NSTAGE];
    float* bufs[NSTAGE];
    #pragma unroll
    for (int s = 0; s < NSTAGE; s++) {
        mbar[s]   = base + 8 * s;
        bufadr[s] = base + 1024 + s * ROW_BYTES;
        bufs[s]   = (float*)(smem_raw + 1024 + s * ROW_BYTES);
    }

    const int tid  = threadIdx.x;
    const int wid  = tid >> 5;
    const int lane = tid & 31;

    if (tid == 0) {
        #pragma unroll
        for (int s = 0; s < NSTAGE; s++) mbar_init(mbar[s], 1);
    }
    __syncthreads();

    if (tid == 0) {
        #pragma unroll
        for (int p = 0; p < 2; p++) {
            int r = blockIdx.x + p * PIPE_GRID;
            if (r < NUM_SRC) {
                mbar_expect_tx(mbar[p], ROW_BYTES);
                #pragma unroll
                for (int c = 0; c < 4; c++)
                    bulk_g2s(bufadr[p] + c * (ROW_BYTES / 4),
                             (const char*)(table + (size_t)r * NUM_SRC) + c * (ROW_BYTES / 4),
                             ROW_BYTES / 4, mbar[p]);
            }
        }
    }
    if (wid == 0) {
        int r = blockIdx.x;
        int d = g_deg[r]; if (d > USE_CAP) d = USE_CAP;
        if (lane == 0) s_n[0] = d;
        for (int u = lane; u < d; u += 32) s_uses[u] = g_uses[r * USE_CAP + u];
    }
    __syncthreads();

    int ph[NSTAGE] = {0, 0, 0};
    int i = 0;
    for (int row = blockIdx.x; row < NUM_SRC; row += PIPE_GRID, i++) {
        const int st   = i % NSTAGE;
        const int slot = i & 1;

        int nxt2 = row + 2 * PIPE_GRID;
        if (nxt2 < NUM_SRC && tid == 0) {
            int ns = (i + 2) % NSTAGE;
            mbar_expect_tx(mbar[ns], ROW_BYTES);
            #pragma unroll
            for (int c = 0; c < 4; c++)
                bulk_g2s(bufadr[ns] + c * (ROW_BYTES / 4),
                         (const char*)(table + (size_t)nxt2 * NUM_SRC) + c * (ROW_BYTES / 4),
                         ROW_BYTES / 4, mbar[ns]);
        }

        if (wid == 31) {
            int r = row + PIPE_GRID;
            int d = 0;
            if (r < NUM_SRC) { d = g_deg[r]; if (d > USE_CAP) d = USE_CAP; }
            if (lane == 0) s_n[slot ^ 1] = d;
            for (int u = lane; u < d; u += 32)
                s_uses[(slot ^ 1) * USE_CAP + u] = g_uses[r * USE_CAP + u];
        }

        mbar_wait(mbar[st], ph[st]);
        ph[st] ^= 1;
        const float* srow = bufs[st];

        const int n = s_n[slot];
        for (int u = wid; u < n; u += 32) {
            int t   = s_uses[slot * USE_CAP + u];
            int bse = t - (t % N_NBR);
            float* out = &g_tile[(size_t)t * N_NBR];
            if (lane < N_NBR) {
                out[lane] = srow[g_idx[bse + lane]];
                int j = lane + 32;
                if (j < N_NBR) out[j] = srow[g_idx[bse + j]];
            }
        }
        __syncthreads();
    }
}

// K4: greedy — warp per tile; row0 register-resident, row1 + cache in smem.
__global__ __launch_bounds__(128, 5) void dgrec_greedy_kernel(
    const float* __restrict__ h_src,
    float* __restrict__ out)
{
    __shared__ __align__(16) float sm[4 * W_STRIDE];   // 43008 B

    const int w    = threadIdx.x >> 5;
    const int lane = threadIdx.x & 31;
    const int b    = blockIdx.x * 4 + w;

    float* s     = &sm[w * W_STRIDE];
    float* cache = &sm[w * W_STRIDE + W_CACHE];
    int*   sels  = (int*)&sm[w * W_STRIDE + W_SELS];
    int*   sidx  = (int*)&sm[w * W_STRIDE + W_SIDX];
    float* nrmk  = &sm[w * W_STRIDE + W_NRMK];

    // Warp-coalesced tile load: 625 float4, scatter to pitch-52 layout
    {
        const float4* tsrc4 = (const float4*)(g_tile + (size_t)b * N_NBR * N_NBR);
        for (int q = lane; q < (N_NBR * N_NBR) / 4; q += 32) {
            float4 v = tsrc4[q];
            int t = q * 4;
            int i0 = t / N_NBR;         s[i0 * WPITCH + (t     - i0 * N_NBR)] = v.x;
            int i1 = (t + 1) / N_NBR;   s[i1 * WPITCH + (t + 1 - i1 * N_NBR)] = v.y;
            int i2 = (t + 2) / N_NBR;   s[i2 * WPITCH + (t + 2 - i2 * N_NBR)] = v.z;
            int i3 = (t + 3) / N_NBR;   s[i3 * WPITCH + (t + 3 - i3 * N_NBR)] = v.w;
        }
        cache[lane] = 0.0f;
        if (lane < 20) cache[lane + 32] = 0.0f;
    }
    __syncwarp();

    const int row0   = lane;
    const int row1   = lane + 32;
    const bool has1  = (row1 < N_NBR);
    const float4* s1 = (const float4*)&s[(has1 ? row1 : row0) * WPITCH];
    const float4* c4 = (const float4*)cache;

    // row0 register-resident: 12 float4 + 2 scalars (one-time LDS)
    float4 r0[12];
    float  r48, r49;
    {
        const float4* s0 = (const float4*)&s[row0 * WPITCH];
        #pragma unroll
        for (int q = 0; q < 12; q++) r0[q] = s0[q];
        r48 = s[row0 * WPITCH + 48];
        r49 = s[row0 * WPITCH + 49];
    }

    for (int k = 0; k < K_SEL; k++) {
        // gains: ascending j, single accumulation chain per row (order unchanged)
        float g0 = 0.0f, g1 = 0.0f;
        #pragma unroll
        for (int q = 0; q < 12; q++) {          // j = 0..47
            float4 c = c4[q];
            float4 a = r0[q];
            float4 d = s1[q];
            g0 += fmaxf(a.x - c.x, 0.0f);  g1 += fmaxf(d.x - c.x, 0.0f);
            g0 += fmaxf(a.y - c.y, 0.0f);  g1 += fmaxf(d.y - c.y, 0.0f);
            g0 += fmaxf(a.z - c.z, 0.0f);  g1 += fmaxf(d.z - c.z, 0.0f);
            g0 += fmaxf(a.w - c.w, 0.0f);  g1 += fmaxf(d.w - c.w, 0.0f);
        }
        {
            float c48 = cache[48], c49 = cache[49];
            g0 += fmaxf(r48 - c48, 0.0f);
            g0 += fmaxf(r49 - c49, 0.0f);
            g1 += fmaxf(s[(has1 ? row1 : row0) * WPITCH + 48] - c48, 0.0f);
            g1 += fmaxf(s[(has1 ? row1 : row0) * WPITCH + 49] - c49, 0.0f);
        }

        float g; int idx;
        if (has1 && g1 > g0) { g = g1; idx = row1; }
        else                 { g = g0; idx = row0; }
        #pragma unroll
        for (int o = 16; o > 0; o >>= 1) {
            float og = __shfl_down_sync(0xffffffffu, g, o);
            int   oi = __shfl_down_sync(0xffffffffu, idx, o);
            if (og > g || (og == g && oi < idx)) { g = og; idx = oi; }
        }
        int sel = __shfl_sync(0xffffffffu, idx, 0);
        if (lane == 0) sels[k] = sel;

        const float* srw = &s[sel * WPITCH];
        cache[lane] = fmaxf(cache[lane], srw[lane]);
        if (has1) cache[row1] = fmaxf(cache[row1], srw[row1]);
        __syncwarp();
    }

    if (lane < K_SEL) {
        int idx2 = g_idx[b * N_NBR + sels[lane]];
        sidx[lane] = idx2;
        int d = g_deg[idx2];
        if (d < 1) d = 1;
        nrmk[lane] = rsqrtf((float)d);
    }
    __syncwarp();

    float acc0 = 0.0f, acc1 = 0.0f;
    #pragma unroll
    for (int k = 0; k < K_SEL; k++) {
        const float* hr = &h_src[(size_t)sidx[k] * D_FEAT];
        float nk = nrmk[k];
        acc0 += hr[lane]      * nk;
        acc1 += hr[lane + 32] * nk;
    }
    out[(size_t)b * D_FEAT + lane]      = acc0 * 0.1414213562373095f;
    out[(size_t)b * D_FEAT + lane + 32] = acc1 * 0.1414213562373095f;
}

extern "C" void kernel_launch(void* const* d_in, const int* in_sizes, int n_in,
                              void* d_out, int out_size) {
    const float* h_src = nullptr;
    const float* table = nullptr;
    const void*  nbrs  = nullptr;
    for (int i = 0; i < n_in; i++) {
        long long sz = in_sizes[i];
        if (sz == (long long)NUM_SRC * NUM_SRC)      table = (const float*)d_in[i];
        else if (sz == (long long)NUM_SRC * D_FEAT)  h_src = (const float*)d_in[i];
        else if (sz == (long long)TOTAL_IDX)         nbrs  = d_in[i];
    }
    float* out = (float*)d_out;

    const int smem_bytes = 1024 + NSTAGE * ROW_BYTES;
    cudaFuncSetAttribute(row_gather_pipe, cudaFuncAttributeMaxDynamicSharedMemorySize,
                         smem_bytes);

    prep_zero_detect<<<(NUM_SRC + 255) / 256, 256>>>((const int*)nbrs);
    prep_convert_hist_fill<<<(TOTAL_IDX + 255) / 256, 256>>>(nbrs);
    row_gather_pipe<<<PIPE_GRID, 1024, smem_bytes>>>(table);
    dgrec_greedy_kernel<<<NUM_DST / 4, 128>>>(h_src, out);
}